// round 2
// baseline (speedup 1.0000x reference)
#include <cuda_runtime.h>
#include <cuda_bf16.h>
#include <cstdint>

// Problem constants (from reference): N=100000 nodes, E=1600000 edges, D=128, L=4
#define DNN   128
#define MAXN  100000
#define MAXE  1600000
#define EPS   1e-5f

// Static device scratch (no cudaMalloc anywhere — _HX_ENFORCE-safe)
__device__ float g_agg[(size_t)MAXN * DNN];
__device__ float g_h0 [(size_t)MAXN * DNN];
__device__ float g_h1 [(size_t)MAXN * DNN];
__device__ int   g_deg   [MAXN + 1];
__device__ int   g_off   [MAXN + 1];
__device__ int   g_cursor[MAXN + 1];
__device__ int   g_esrc  [MAXE];

// ---------------------------------------------------------------------------
// CSR build: histogram of dst -> exclusive scan -> reorder src by dst bucket.
// ---------------------------------------------------------------------------
__global__ __launch_bounds__(256)
void hist_kernel(const int* __restrict__ dst, int* __restrict__ deg, int E)
{
    int e = blockIdx.x * blockDim.x + threadIdx.x;
    if (e < E) atomicAdd(&deg[dst[e]], 1);
}

// One block, 1024 threads; chunked exclusive scan over Nn counters.
__global__ __launch_bounds__(1024)
void scan_kernel(const int* __restrict__ deg, int* __restrict__ off,
                 int* __restrict__ cur, int Nn, int E)
{
    __shared__ int part[1024];
    const int tid   = threadIdx.x;
    const int chunk = (Nn + 1023) / 1024;
    const int s0    = tid * chunk;
    const int s1    = min(s0 + chunk, Nn);

    int sum = 0;
    for (int i = s0; i < s1; i++) sum += deg[i];
    part[tid] = sum;
    __syncthreads();

    // Hillis–Steele inclusive scan over 1024 partials
    for (int stp = 1; stp < 1024; stp <<= 1) {
        int v = (tid >= stp) ? part[tid - stp] : 0;
        __syncthreads();
        part[tid] += v;
        __syncthreads();
    }
    int base = (tid == 0) ? 0 : part[tid - 1];   // exclusive prefix for chunk

    for (int i = s0; i < s1; i++) {
        off[i] = base;
        cur[i] = base;
        base  += deg[i];
    }
    if (tid == 0) off[Nn] = E;
}

__global__ __launch_bounds__(256)
void reorder_kernel(const int* __restrict__ src, const int* __restrict__ dst,
                    int* __restrict__ cur, int* __restrict__ esrc, int E)
{
    int e = blockIdx.x * blockDim.x + threadIdx.x;
    if (e >= E) return;
    int pos = atomicAdd(&cur[dst[e]], 1);
    esrc[pos] = src[e];
}

// ---------------------------------------------------------------------------
// Gather aggregation: agg[n] = sum over in-neighbors s of h[s].
// One warp per node; lane holds float4 (4 columns). Index prefetch to overlap
// the dependent esrc -> row-load chain.
// ---------------------------------------------------------------------------
__global__ __launch_bounds__(256)
void gather_kernel(const float* __restrict__ h,
                   const int* __restrict__ esrc,
                   const int* __restrict__ off,
                   float* __restrict__ agg,
                   int Nn)
{
    int node = blockIdx.x * (blockDim.x >> 5) + (threadIdx.x >> 5);
    int lane = threadIdx.x & 31;
    if (node >= Nn) return;

    int b = off[node];
    int e = off[node + 1];

    float4 acc = make_float4(0.f, 0.f, 0.f, 0.f);
    int s = (b < e) ? esrc[b] : 0;
    for (int i = b; i < e; i++) {
        int snext = (i + 1 < e) ? esrc[i + 1] : 0;
        float4 v = reinterpret_cast<const float4*>(h + (size_t)s * DNN)[lane];
        acc.x += v.x; acc.y += v.y; acc.z += v.z; acc.w += v.w;
        s = snext;
    }
    reinterpret_cast<float4*>(agg + (size_t)node * DNN)[lane] = acc;
}

// ---------------------------------------------------------------------------
// Fused conv layer:
//   out = [agg | h] @ [[W_rel],[W_root]] + b_rel   (K = 256, Ncols = 128)
// MODE 0: relu -> LayerNorm                (input layer)
// MODE 1: +h residual -> relu -> LayerNorm (middle layers)
// MODE 2: plain write                      (output layer)
//
// Block: 256 threads = 8 warps. Tile: 32 rows x 128 cols (full row -> LN in
// warp shuffles; warp ty owns rows ty*4..ty*4+3 entirely).
// ---------------------------------------------------------------------------
template <int MODE>
__global__ __launch_bounds__(256)
void conv_kernel(const float* __restrict__ agg,
                 const float* __restrict__ hin,
                 const float* __restrict__ Wr,    // [128][128] row-major (k,c)
                 const float* __restrict__ br,    // [128]
                 const float* __restrict__ Wrt,   // [128][128]
                 const float* __restrict__ gamma,
                 const float* __restrict__ beta,
                 float* __restrict__ out,
                 int Nn)
{
    __shared__ float xs[32][32];    // [m][k_local]
    __shared__ float ws[32][128];   // [k_local][c]

    const int tid = threadIdx.x;
    const int tx  = tid & 31;       // col group
    const int ty  = tid >> 5;       // warp id / row group
    const int rowBase = blockIdx.x * 32;

    float acc[4][4];
#pragma unroll
    for (int i = 0; i < 4; i++)
#pragma unroll
        for (int j = 0; j < 4; j++) acc[i][j] = 0.0f;

    for (int kt = 0; kt < 8; kt++) {
        const int kbase = kt * 32;

        // xs: 1024 elems, 4 per thread; coalesced along k.
#pragma unroll
        for (int p = 0; p < 4; p++) {
            int e = tid + p * 256;
            int m = e >> 5;
            int k = e & 31;
            int r = rowBase + m;
            int kg = kbase + k;
            float val = 0.0f;
            if (r < Nn) {
                val = (kg < DNN) ? agg[(size_t)r * DNN + kg]
                                 : hin[(size_t)r * DNN + (kg - DNN)];
            }
            xs[m][k] = val;
        }

        // ws: 4096 elems as 1024 float4, 4 per thread; coalesced along c.
#pragma unroll
        for (int p = 0; p < 4; p++) {
            int q = tid + p * 256;
            int k = q >> 5;
            int c = (q & 31) * 4;
            int kg = kbase + k;
            const float* wsrc = (kg < DNN) ? (Wr  + (size_t)kg * DNN + c)
                                           : (Wrt + (size_t)(kg - DNN) * DNN + c);
            *reinterpret_cast<float4*>(&ws[k][c]) =
                *reinterpret_cast<const float4*>(wsrc);
        }

        __syncthreads();

#pragma unroll
        for (int k = 0; k < 32; k++) {
            float4 w = *reinterpret_cast<const float4*>(&ws[k][tx * 4]);
            float x0 = xs[ty * 4 + 0][k];
            float x1 = xs[ty * 4 + 1][k];
            float x2 = xs[ty * 4 + 2][k];
            float x3 = xs[ty * 4 + 3][k];
            acc[0][0] = fmaf(x0, w.x, acc[0][0]);
            acc[0][1] = fmaf(x0, w.y, acc[0][1]);
            acc[0][2] = fmaf(x0, w.z, acc[0][2]);
            acc[0][3] = fmaf(x0, w.w, acc[0][3]);
            acc[1][0] = fmaf(x1, w.x, acc[1][0]);
            acc[1][1] = fmaf(x1, w.y, acc[1][1]);
            acc[1][2] = fmaf(x1, w.z, acc[1][2]);
            acc[1][3] = fmaf(x1, w.w, acc[1][3]);
            acc[2][0] = fmaf(x2, w.x, acc[2][0]);
            acc[2][1] = fmaf(x2, w.y, acc[2][1]);
            acc[2][2] = fmaf(x2, w.z, acc[2][2]);
            acc[2][3] = fmaf(x2, w.w, acc[2][3]);
            acc[3][0] = fmaf(x3, w.x, acc[3][0]);
            acc[3][1] = fmaf(x3, w.y, acc[3][1]);
            acc[3][2] = fmaf(x3, w.z, acc[3][2]);
            acc[3][3] = fmaf(x3, w.w, acc[3][3]);
        }

        __syncthreads();
    }

    // Epilogue
    const int c0 = tx * 4;
    const float4 bv = *reinterpret_cast<const float4*>(br + c0);
    float4 gv, btv;
    if (MODE < 2) {
        gv  = *reinterpret_cast<const float4*>(gamma + c0);
        btv = *reinterpret_cast<const float4*>(beta  + c0);
    }

#pragma unroll
    for (int i = 0; i < 4; i++) {
        int r = rowBase + ty * 4 + i;
        bool valid = (r < Nn);

        float v0 = acc[i][0] + bv.x;
        float v1 = acc[i][1] + bv.y;
        float v2 = acc[i][2] + bv.z;
        float v3 = acc[i][3] + bv.w;

        if (MODE == 1) {
            if (valid) {
                float4 hres = *reinterpret_cast<const float4*>(
                    hin + (size_t)r * DNN + c0);
                v0 += hres.x; v1 += hres.y; v2 += hres.z; v3 += hres.w;
            }
        }

        if (MODE < 2) {
            v0 = fmaxf(v0, 0.0f);
            v1 = fmaxf(v1, 0.0f);
            v2 = fmaxf(v2, 0.0f);
            v3 = fmaxf(v3, 0.0f);

            float s  = v0 + v1 + v2 + v3;
            float s2 = v0 * v0 + v1 * v1 + v2 * v2 + v3 * v3;
#pragma unroll
            for (int off = 16; off >= 1; off >>= 1) {
                s  += __shfl_xor_sync(0xFFFFFFFFu, s,  off);
                s2 += __shfl_xor_sync(0xFFFFFFFFu, s2, off);
            }
            float mean = s * (1.0f / 128.0f);
            float var  = s2 * (1.0f / 128.0f) - mean * mean;
            float inv  = rsqrtf(var + EPS);

            v0 = (v0 - mean) * inv * gv.x + btv.x;
            v1 = (v1 - mean) * inv * gv.y + btv.y;
            v2 = (v2 - mean) * inv * gv.z + btv.z;
            v3 = (v3 - mean) * inv * gv.w + btv.w;
        }

        if (valid) {
            *reinterpret_cast<float4*>(out + (size_t)r * DNN + c0) =
                make_float4(v0, v1, v2, v3);
        }
    }
}

// ---------------------------------------------------------------------------
// Launch.  Inputs (metadata order): in_feat[N,128] f32, edge_index[2,E] i32,
// W_rel[4,128,128] f32, b_rel[4,128] f32, W_root[4,128,128] f32,
// ln_gamma[128] f32, ln_beta[128] f32.  Output: [N,128] f32.
// ---------------------------------------------------------------------------
extern "C" void kernel_launch(void* const* d_in, const int* in_sizes, int n_in,
                              void* d_out, int out_size)
{
    const float* in_feat = (const float*)d_in[0];
    const int*   ei      = (const int*)  d_in[1];
    const float* W_rel   = (const float*)d_in[2];
    const float* b_rel   = (const float*)d_in[3];
    const float* W_root  = (const float*)d_in[4];
    const float* gamma   = (const float*)d_in[5];
    const float* beta    = (const float*)d_in[6];
    float* out = (float*)d_out;

    const int Nn = in_sizes[0] / DNN;
    const int E  = in_sizes[1] / 2;
    const int* src = ei;
    const int* dst = ei + E;

    float *agg, *h0, *h1;
    int *deg, *off, *cur, *esrc;
    cudaGetSymbolAddress((void**)&agg,  g_agg);
    cudaGetSymbolAddress((void**)&h0,   g_h0);
    cudaGetSymbolAddress((void**)&h1,   g_h1);
    cudaGetSymbolAddress((void**)&deg,  g_deg);
    cudaGetSymbolAddress((void**)&off,  g_off);
    cudaGetSymbolAddress((void**)&cur,  g_cursor);
    cudaGetSymbolAddress((void**)&esrc, g_esrc);

    const int edgeBlocks   = (E + 255) / 256;
    const int gatherBlocks = (Nn + 7) / 8;       // 8 warps (nodes) per block
    const int convBlocks   = (Nn + 31) / 32;
    const size_t WSTRIDE   = (size_t)DNN * DNN;

    // ---- CSR build (once; reused by all 4 layers) ----
    cudaMemsetAsync(deg, 0, (size_t)(Nn + 1) * sizeof(int));
    hist_kernel<<<edgeBlocks, 256>>>(dst, deg, E);
    scan_kernel<<<1, 1024>>>(deg, off, cur, Nn, E);
    reorder_kernel<<<edgeBlocks, 256>>>(src, dst, cur, esrc, E);

    // ---- Layer 0: conv(in_feat) -> relu -> LN  => h0 ----
    gather_kernel<<<gatherBlocks, 256>>>(in_feat, esrc, off, agg, Nn);
    conv_kernel<0><<<convBlocks, 256>>>(agg, in_feat,
                                        W_rel + 0 * WSTRIDE, b_rel + 0 * DNN,
                                        W_root + 0 * WSTRIDE, gamma, beta,
                                        h0, Nn);

    // ---- Layer 1: conv(h0) + h0 -> relu -> LN  => h1 ----
    gather_kernel<<<gatherBlocks, 256>>>(h0, esrc, off, agg, Nn);
    conv_kernel<1><<<convBlocks, 256>>>(agg, h0,
                                        W_rel + 1 * WSTRIDE, b_rel + 1 * DNN,
                                        W_root + 1 * WSTRIDE, gamma, beta,
                                        h1, Nn);

    // ---- Layer 2: conv(h1) + h1 -> relu -> LN  => h0 ----
    gather_kernel<<<gatherBlocks, 256>>>(h1, esrc, off, agg, Nn);
    conv_kernel<1><<<convBlocks, 256>>>(agg, h1,
                                        W_rel + 2 * WSTRIDE, b_rel + 2 * DNN,
                                        W_root + 2 * WSTRIDE, gamma, beta,
                                        h0, Nn);

    // ---- Layer 3 (output): conv(h0) only => d_out ----
    gather_kernel<<<gatherBlocks, 256>>>(h0, esrc, off, agg, Nn);
    conv_kernel<2><<<convBlocks, 256>>>(agg, h0,
                                        W_rel + 3 * WSTRIDE, b_rel + 3 * DNN,
                                        W_root + 3 * WSTRIDE, gamma, beta,
                                        out, Nn);
}

// round 5
// speedup vs baseline: 1.1116x; 1.1116x over previous
#include <cuda_runtime.h>
#include <cuda_bf16.h>
#include <cstdint>

// Problem constants: N=100000 nodes, E=1600000 edges, D=128, L=4
#define DNN   128
#define MAXN  100000
#define MAXE  1600000
#define EPS   1e-5f

// Static device scratch (no cudaMalloc anywhere)
__device__ float g_agg[(size_t)MAXN * DNN];
__device__ float g_h0 [(size_t)MAXN * DNN];
__device__ float g_h1 [(size_t)MAXN * DNN];
__device__ int   g_deg   [MAXN + 1];
__device__ int   g_off   [MAXN + 1];
__device__ int   g_cursor[MAXN + 1];
__device__ int   g_esrc  [MAXE];

// ---------------------------------------------------------------------------
// CSR build: histogram of dst -> exclusive scan -> reorder src by dst bucket.
// ---------------------------------------------------------------------------
__global__ __launch_bounds__(256)
void hist_kernel(const int* __restrict__ dst, int* __restrict__ deg, int E)
{
    int e = blockIdx.x * blockDim.x + threadIdx.x;
    if (e < E) atomicAdd(&deg[dst[e]], 1);
}

__global__ __launch_bounds__(1024)
void scan_kernel(const int* __restrict__ deg, int* __restrict__ off,
                 int* __restrict__ cur, int Nn, int E)
{
    __shared__ int part[1024];
    const int tid   = threadIdx.x;
    const int chunk = (Nn + 1023) / 1024;
    const int s0    = tid * chunk;
    const int s1    = min(s0 + chunk, Nn);

    int sum = 0;
    for (int i = s0; i < s1; i++) sum += deg[i];
    part[tid] = sum;
    __syncthreads();

    for (int stp = 1; stp < 1024; stp <<= 1) {
        int v = (tid >= stp) ? part[tid - stp] : 0;
        __syncthreads();
        part[tid] += v;
        __syncthreads();
    }
    int base = (tid == 0) ? 0 : part[tid - 1];

    for (int i = s0; i < s1; i++) {
        off[i] = base;
        cur[i] = base;
        base  += deg[i];
    }
    if (tid == 0) off[Nn] = E;
}

__global__ __launch_bounds__(256)
void reorder_kernel(const int* __restrict__ src, const int* __restrict__ dst,
                    int* __restrict__ cur, int* __restrict__ esrc, int E)
{
    int e = blockIdx.x * blockDim.x + threadIdx.x;
    if (e >= E) return;
    int pos = atomicAdd(&cur[dst[e]], 1);
    esrc[pos] = src[e];
}

// ---------------------------------------------------------------------------
// Gather aggregation: agg[n] = sum over in-neighbors s of h[s].
// One warp per node; lane holds float4. Index prefetch.
// ---------------------------------------------------------------------------
__global__ __launch_bounds__(256)
void gather_kernel(const float* __restrict__ h,
                   const int* __restrict__ esrc,
                   const int* __restrict__ off,
                   float* __restrict__ agg,
                   int Nn)
{
    int node = blockIdx.x * (blockDim.x >> 5) + (threadIdx.x >> 5);
    int lane = threadIdx.x & 31;
    if (node >= Nn) return;

    int b = off[node];
    int e = off[node + 1];

    float4 acc = make_float4(0.f, 0.f, 0.f, 0.f);
    int s = (b < e) ? esrc[b] : 0;
    for (int i = b; i < e; i++) {
        int snext = (i + 1 < e) ? esrc[i + 1] : 0;
        float4 v = reinterpret_cast<const float4*>(h + (size_t)s * DNN)[lane];
        acc.x += v.x; acc.y += v.y; acc.z += v.z; acc.w += v.w;
        s = snext;
    }
    reinterpret_cast<float4*>(agg + (size_t)node * DNN)[lane] = acc;
}

// ---------------------------------------------------------------------------
// tf32 helpers
// ---------------------------------------------------------------------------
__device__ __forceinline__ void tf32split(float x, float& hi, float& lo)
{
    uint32_t hb;
    asm("cvt.rna.tf32.f32 %0, %1;" : "=r"(hb) : "f"(x));
    float hf = __uint_as_float(hb);
    float rem = x - hf;
    uint32_t lb;
    asm("cvt.rna.tf32.f32 %0, %1;" : "=r"(lb) : "f"(rem));
    hi = hf;
    lo = __uint_as_float(lb);
}

#define MMA_TF32(d, a, b)                                                     \
    asm volatile(                                                             \
        "mma.sync.aligned.m16n8k8.row.col.f32.tf32.tf32.f32 "                 \
        "{%0,%1,%2,%3},{%4,%5,%6,%7},{%8,%9},{%0,%1,%2,%3};"                  \
        : "+f"((d)[0]), "+f"((d)[1]), "+f"((d)[2]), "+f"((d)[3])              \
        : "r"((a)[0]), "r"((a)[1]), "r"((a)[2]), "r"((a)[3]),                 \
          "r"((b)[0]), "r"((b)[1]))

// ---------------------------------------------------------------------------
// Tensor-core fused conv layer (3xTF32 compensated => ~fp32 accuracy):
//   out = [agg | h] @ [[W_rel],[W_root]] + b_rel     (K=256, Ncols=128)
// MODE 0: relu -> LN     MODE 1: +h -> relu -> LN     MODE 2: plain
//
// Block 256 thr (8 warps), tile 64 rows x 128 cols; warp grid 2x4, warp tile
// 32x32. K in 16 stages of 16 (two k8 MMA sub-steps per stage).
// ---------------------------------------------------------------------------
template <int MODE>
__global__ __launch_bounds__(256)
void conv_tc_kernel(const float* __restrict__ agg,
                    const float* __restrict__ hin,
                    const float* __restrict__ Wr,    // [128][128] (k,c)
                    const float* __restrict__ br,    // [128]
                    const float* __restrict__ Wrt,   // [128][128]
                    const float* __restrict__ gamma,
                    const float* __restrict__ beta,
                    float* __restrict__ out,
                    int Nn)
{
    __shared__ union SM {
        struct {
            float xh[64][20];    // pad 20: conflict-free A-frag LDS
            float xl[64][20];
            float wh[16][136];   // pad 136: conflict-free B-frag LDS
            float wl[16][136];
        } s;
        float ob[64][132];       // epilogue buffer
    } sm;

    const int tid  = threadIdx.x;
    const int lane = tid & 31;
    const int wid  = tid >> 5;
    const int wr   = wid >> 2;       // warp row: 0..1
    const int wc   = wid & 3;        // warp col: 0..3
    const int rowBase = blockIdx.x * 64;
    const int qr = lane >> 2;        // quad row 0..7
    const int qc = lane & 3;         // quad col 0..3

    float acc[2][4][4];
#pragma unroll
    for (int m = 0; m < 2; m++)
#pragma unroll
        for (int n = 0; n < 4; n++)
#pragma unroll
            for (int j = 0; j < 4; j++) acc[m][n][j] = 0.0f;

    for (int kt = 0; kt < 16; kt++) {
        const int kbase = kt * 16;

        // ---- load X tile (64 rows x 16 k) with tf32 split ----
#pragma unroll
        for (int p = 0; p < 4; p++) {
            int e = tid + p * 256;
            int m = e >> 4;
            int k = e & 15;
            int r = rowBase + m;
            int kg = kbase + k;
            float v = 0.0f;
            if (r < Nn) {
                v = (kg < DNN) ? agg[r * DNN + kg]
                               : hin[r * DNN + (kg - DNN)];
            }
            float h, l;
            tf32split(v, h, l);
            sm.s.xh[m][k] = h;
            sm.s.xl[m][k] = l;
        }

        // ---- load W tile (16 k x 128 c) with tf32 split ----
#pragma unroll
        for (int p = 0; p < 2; p++) {
            int q = tid + p * 256;
            int k = q >> 5;
            int c = (q & 31) * 4;
            int kg = kbase + k;
            const float* wsrc = (kg < DNN) ? (Wr  + kg * DNN + c)
                                           : (Wrt + (kg - DNN) * DNN + c);
            float4 w = *reinterpret_cast<const float4*>(wsrc);
            float h0_, l0_, h1_, l1_, h2_, l2_, h3_, l3_;
            tf32split(w.x, h0_, l0_);
            tf32split(w.y, h1_, l1_);
            tf32split(w.z, h2_, l2_);
            tf32split(w.w, h3_, l3_);
            sm.s.wh[k][c + 0] = h0_;  sm.s.wl[k][c + 0] = l0_;
            sm.s.wh[k][c + 1] = h1_;  sm.s.wl[k][c + 1] = l1_;
            sm.s.wh[k][c + 2] = h2_;  sm.s.wl[k][c + 2] = l2_;
            sm.s.wh[k][c + 3] = h3_;  sm.s.wl[k][c + 3] = l3_;
        }

        __syncthreads();

        // ---- two k8 MMA sub-steps ----
#pragma unroll
        for (int s = 0; s < 2; s++) {
            const int ko = s * 8;

            uint32_t Ah[2][4], Al[2][4], Bh[4][2], Bl[4][2];
            const int ac = ko + qc;
#pragma unroll
            for (int m = 0; m < 2; m++) {
                int r = wr * 32 + m * 16 + qr;
                Ah[m][0] = __float_as_uint(sm.s.xh[r    ][ac    ]);
                Ah[m][1] = __float_as_uint(sm.s.xh[r + 8][ac    ]);
                Ah[m][2] = __float_as_uint(sm.s.xh[r    ][ac + 4]);
                Ah[m][3] = __float_as_uint(sm.s.xh[r + 8][ac + 4]);
                Al[m][0] = __float_as_uint(sm.s.xl[r    ][ac    ]);
                Al[m][1] = __float_as_uint(sm.s.xl[r + 8][ac    ]);
                Al[m][2] = __float_as_uint(sm.s.xl[r    ][ac + 4]);
                Al[m][3] = __float_as_uint(sm.s.xl[r + 8][ac + 4]);
            }
            const int kr = ko + qc;
#pragma unroll
            for (int n = 0; n < 4; n++) {
                int col = wc * 32 + n * 8 + qr;
                Bh[n][0] = __float_as_uint(sm.s.wh[kr    ][col]);
                Bh[n][1] = __float_as_uint(sm.s.wh[kr + 4][col]);
                Bl[n][0] = __float_as_uint(sm.s.wl[kr    ][col]);
                Bl[n][1] = __float_as_uint(sm.s.wl[kr + 4][col]);
            }

#pragma unroll
            for (int m = 0; m < 2; m++)
#pragma unroll
                for (int n = 0; n < 4; n++) {
                    MMA_TF32(acc[m][n], Ah[m], Bh[n]);
                    MMA_TF32(acc[m][n], Ah[m], Bl[n]);
                    MMA_TF32(acc[m][n], Al[m], Bh[n]);
                }
        }

        __syncthreads();
    }

    // ---- epilogue: acc -> smem, then per-row LayerNorm ----
#pragma unroll
    for (int m = 0; m < 2; m++) {
        int r0 = wr * 32 + m * 16 + qr;
#pragma unroll
        for (int n = 0; n < 4; n++) {
            int c = wc * 32 + n * 8 + qc * 2;
            sm.ob[r0    ][c    ] = acc[m][n][0];
            sm.ob[r0    ][c + 1] = acc[m][n][1];
            sm.ob[r0 + 8][c    ] = acc[m][n][2];
            sm.ob[r0 + 8][c + 1] = acc[m][n][3];
        }
    }
    __syncthreads();

    // Warp wid handles rows wid*8 .. wid*8+7; lane holds 4 cols (lane*4).
    const int c0 = lane * 4;
    const float4 bv = *reinterpret_cast<const float4*>(br + c0);
    float4 gv, btv;
    if (MODE < 2) {
        gv  = *reinterpret_cast<const float4*>(gamma + c0);
        btv = *reinterpret_cast<const float4*>(beta  + c0);
    }

#pragma unroll
    for (int i = 0; i < 8; i++) {
        int lr = wid * 8 + i;
        int r  = rowBase + lr;
        bool valid = (r < Nn);

        float4 v = *reinterpret_cast<const float4*>(&sm.ob[lr][c0]);
        float v0 = v.x + bv.x;
        float v1 = v.y + bv.y;
        float v2 = v.z + bv.z;
        float v3 = v.w + bv.w;

        if (MODE == 1) {
            if (valid) {
                float4 hr = *reinterpret_cast<const float4*>(hin + r * DNN + c0);
                v0 += hr.x; v1 += hr.y; v2 += hr.z; v3 += hr.w;
            }
        }

        if (MODE < 2) {
            v0 = fmaxf(v0, 0.0f);
            v1 = fmaxf(v1, 0.0f);
            v2 = fmaxf(v2, 0.0f);
            v3 = fmaxf(v3, 0.0f);

            float s  = v0 + v1 + v2 + v3;
            float s2 = v0 * v0 + v1 * v1 + v2 * v2 + v3 * v3;
#pragma unroll
            for (int off = 16; off >= 1; off >>= 1) {
                s  += __shfl_xor_sync(0xFFFFFFFFu, s,  off);
                s2 += __shfl_xor_sync(0xFFFFFFFFu, s2, off);
            }
            float mean = s * (1.0f / 128.0f);
            float var  = s2 * (1.0f / 128.0f) - mean * mean;
            float inv  = rsqrtf(var + EPS);

            v0 = (v0 - mean) * inv * gv.x + btv.x;
            v1 = (v1 - mean) * inv * gv.y + btv.y;
            v2 = (v2 - mean) * inv * gv.z + btv.z;
            v3 = (v3 - mean) * inv * gv.w + btv.w;
        }

        if (valid) {
            *reinterpret_cast<float4*>(out + r * DNN + c0) =
                make_float4(v0, v1, v2, v3);
        }
    }
}

// ---------------------------------------------------------------------------
// Launch.  Inputs: in_feat[N,128] f32, edge_index[2,E] i32,
// W_rel[4,128,128], b_rel[4,128], W_root[4,128,128], ln_gamma[128],
// ln_beta[128].  Output: [N,128] f32.
// ---------------------------------------------------------------------------
extern "C" void kernel_launch(void* const* d_in, const int* in_sizes, int n_in,
                              void* d_out, int out_size)
{
    const float* in_feat = (const float*)d_in[0];
    const int*   ei      = (const int*)  d_in[1];
    const float* W_rel   = (const float*)d_in[2];
    const float* b_rel   = (const float*)d_in[3];
    const float* W_root  = (const float*)d_in[4];
    const float* gamma   = (const float*)d_in[5];
    const float* beta    = (const float*)d_in[6];
    float* out = (float*)d_out;

    const int Nn = in_sizes[0] / DNN;
    const int E  = in_sizes[1] / 2;
    const int* src = ei;
    const int* dst = ei + E;

    float *agg, *h0, *h1;
    int *deg, *off, *cur, *esrc;
    cudaGetSymbolAddress((void**)&agg,  g_agg);
    cudaGetSymbolAddress((void**)&h0,   g_h0);
    cudaGetSymbolAddress((void**)&h1,   g_h1);
    cudaGetSymbolAddress((void**)&deg,  g_deg);
    cudaGetSymbolAddress((void**)&off,  g_off);
    cudaGetSymbolAddress((void**)&cur,  g_cursor);
    cudaGetSymbolAddress((void**)&esrc, g_esrc);

    const int edgeBlocks   = (E + 255) / 256;
    const int gatherBlocks = (Nn + 7) / 8;
    const int convBlocks   = (Nn + 63) / 64;
    const size_t WSTRIDE   = (size_t)DNN * DNN;

    // ---- CSR build (reused by all 4 layers) ----
    cudaMemsetAsync(deg, 0, (size_t)(Nn + 1) * sizeof(int));
    hist_kernel<<<edgeBlocks, 256>>>(dst, deg, E);
    scan_kernel<<<1, 1024>>>(deg, off, cur, Nn, E);
    reorder_kernel<<<edgeBlocks, 256>>>(src, dst, cur, esrc, E);

    // ---- Layer 0: conv(in_feat) -> relu -> LN  => h0 ----
    gather_kernel<<<gatherBlocks, 256>>>(in_feat, esrc, off, agg, Nn);
    conv_tc_kernel<0><<<convBlocks, 256>>>(agg, in_feat,
                                           W_rel + 0 * WSTRIDE, b_rel + 0 * DNN,
                                           W_root + 0 * WSTRIDE, gamma, beta,
                                           h0, Nn);

    // ---- Layer 1: conv(h0) + h0 -> relu -> LN  => h1 ----
    gather_kernel<<<gatherBlocks, 256>>>(h0, esrc, off, agg, Nn);
    conv_tc_kernel<1><<<convBlocks, 256>>>(agg, h0,
                                           W_rel + 1 * WSTRIDE, b_rel + 1 * DNN,
                                           W_root + 1 * WSTRIDE, gamma, beta,
                                           h1, Nn);

    // ---- Layer 2: conv(h1) + h1 -> relu -> LN  => h0 ----
    gather_kernel<<<gatherBlocks, 256>>>(h1, esrc, off, agg, Nn);
    conv_tc_kernel<1><<<convBlocks, 256>>>(agg, h1,
                                           W_rel + 2 * WSTRIDE, b_rel + 2 * DNN,
                                           W_root + 2 * WSTRIDE, gamma, beta,
                                           h0, Nn);

    // ---- Layer 3 (output): conv(h0) only => d_out ----
    gather_kernel<<<gatherBlocks, 256>>>(h0, esrc, off, agg, Nn);
    conv_tc_kernel<2><<<convBlocks, 256>>>(agg, h0,
                                           W_rel + 3 * WSTRIDE, b_rel + 3 * DNN,
                                           W_root + 3 * WSTRIDE, gamma, beta,
                                           out, Nn);
}

// round 8
// speedup vs baseline: 1.5364x; 1.3821x over previous
#include <cuda_runtime.h>
#include <cuda_bf16.h>
#include <cstdint>

// Problem constants: N=100000 nodes, E=1600000 edges, D=128, L=4
#define DNN   128
#define MAXN  100000
#define MAXE  1600000
#define EPS   1e-5f

// Static device scratch (no cudaMalloc anywhere)
__device__ float    g_agg[(size_t)MAXN * DNN];
__device__ float    g_h0 [(size_t)MAXN * DNN];
__device__ float    g_h1 [(size_t)MAXN * DNN];
__device__ int      g_deg   [MAXN + 1];
__device__ int      g_off   [MAXN + 1];
__device__ int      g_cursor[MAXN + 1];
__device__ int      g_esrc  [MAXE];
// Pre-split weights: [4 layers][128 k-pairs][136 cols] packed bf16x2 (hi & lo)
#define WPSTRIDE 136
__device__ uint32_t g_whi[4 * 128 * WPSTRIDE];
__device__ uint32_t g_wlo[4 * 128 * WPSTRIDE];

// ---------------------------------------------------------------------------
// bf16 split helpers: x ~= hi + lo  (hi,lo bf16; residual ~2^-18 |x|)
// pack2: element a (even k) in LOW half, b (odd k) in HIGH half.
// ---------------------------------------------------------------------------
__device__ __forceinline__ void bfsplit2(float a, float b,
                                         uint32_t& hi, uint32_t& lo)
{
    __nv_bfloat16 ah = __float2bfloat16(a);
    __nv_bfloat16 bh = __float2bfloat16(b);
    float ar = a - __bfloat162float(ah);
    float br = b - __bfloat162float(bh);
    __nv_bfloat16 al = __float2bfloat16(ar);
    __nv_bfloat16 bl = __float2bfloat16(br);
    hi = ((uint32_t)__bfloat16_as_ushort(bh) << 16) | __bfloat16_as_ushort(ah);
    lo = ((uint32_t)__bfloat16_as_ushort(bl) << 16) | __bfloat16_as_ushort(al);
}

// ---------------------------------------------------------------------------
// W pre-split: stacked K layout [W_rel(128) ; W_root(128)] per layer,
// packed along k into bf16x2 pairs. One thread per packed word.
// ---------------------------------------------------------------------------
__global__ __launch_bounds__(256)
void wsplit_kernel(const float* __restrict__ Wrel,
                   const float* __restrict__ Wroot,
                   uint32_t* __restrict__ whi,
                   uint32_t* __restrict__ wlo)
{
    int idx = blockIdx.x * 256 + threadIdx.x;     // 0 .. 4*128*128-1
    if (idx >= 4 * 128 * 128) return;
    int c = idx & 127;
    int p = (idx >> 7) & 127;                     // k-pair 0..127
    int l = idx >> 14;                            // layer

    int k0 = 2 * p;
    float v0, v1;
    if (p < 64) {                                 // both from W_rel
        v0 = Wrel[(size_t)l * 16384 + k0 * 128 + c];
        v1 = Wrel[(size_t)l * 16384 + (k0 + 1) * 128 + c];
    } else {                                      // both from W_root
        v0 = Wroot[(size_t)l * 16384 + (k0 - 128) * 128 + c];
        v1 = Wroot[(size_t)l * 16384 + (k0 - 127) * 128 + c];
    }
    uint32_t hi, lo;
    bfsplit2(v0, v1, hi, lo);
    size_t o = ((size_t)l * 128 + p) * WPSTRIDE + c;
    whi[o] = hi;
    wlo[o] = lo;
}

// ---------------------------------------------------------------------------
// CSR build: histogram of dst -> exclusive scan -> reorder src by dst bucket.
// ---------------------------------------------------------------------------
__global__ __launch_bounds__(256)
void hist_kernel(const int* __restrict__ dst, int* __restrict__ deg, int E)
{
    int e = blockIdx.x * blockDim.x + threadIdx.x;
    if (e < E) atomicAdd(&deg[dst[e]], 1);
}

__global__ __launch_bounds__(1024)
void scan_kernel(const int* __restrict__ deg, int* __restrict__ off,
                 int* __restrict__ cur, int Nn, int E)
{
    __shared__ int part[1024];
    const int tid   = threadIdx.x;
    const int chunk = (Nn + 1023) / 1024;
    const int s0    = tid * chunk;
    const int s1    = min(s0 + chunk, Nn);

    int sum = 0;
    for (int i = s0; i < s1; i++) sum += deg[i];
    part[tid] = sum;
    __syncthreads();

    for (int stp = 1; stp < 1024; stp <<= 1) {
        int v = (tid >= stp) ? part[tid - stp] : 0;
        __syncthreads();
        part[tid] += v;
        __syncthreads();
    }
    int base = (tid == 0) ? 0 : part[tid - 1];

    for (int i = s0; i < s1; i++) {
        off[i] = base;
        cur[i] = base;
        base  += deg[i];
    }
    if (tid == 0) off[Nn] = E;
}

__global__ __launch_bounds__(256)
void reorder_kernel(const int* __restrict__ src, const int* __restrict__ dst,
                    int* __restrict__ cur, int* __restrict__ esrc, int E)
{
    int e = blockIdx.x * blockDim.x + threadIdx.x;
    if (e >= E) return;
    int pos = atomicAdd(&cur[dst[e]], 1);
    esrc[pos] = src[e];
}

// ---------------------------------------------------------------------------
// Gather aggregation: agg[n] = sum over in-neighbors s of h[s].
// One warp per node; lane holds float4. Index prefetch.
// ---------------------------------------------------------------------------
__global__ __launch_bounds__(256)
void gather_kernel(const float* __restrict__ h,
                   const int* __restrict__ esrc,
                   const int* __restrict__ off,
                   float* __restrict__ agg,
                   int Nn)
{
    int node = blockIdx.x * (blockDim.x >> 5) + (threadIdx.x >> 5);
    int lane = threadIdx.x & 31;
    if (node >= Nn) return;

    int b = off[node];
    int e = off[node + 1];

    float4 acc = make_float4(0.f, 0.f, 0.f, 0.f);
    int s = (b < e) ? esrc[b] : 0;
    for (int i = b; i < e; i++) {
        int snext = (i + 1 < e) ? esrc[i + 1] : 0;
        float4 v = reinterpret_cast<const float4*>(h + (size_t)s * DNN)[lane];
        acc.x += v.x; acc.y += v.y; acc.z += v.z; acc.w += v.w;
        s = snext;
    }
    reinterpret_cast<float4*>(agg + (size_t)node * DNN)[lane] = acc;
}

// ---------------------------------------------------------------------------
// bf16 m16n8k16 MMA (A row-major, B col-major, f32 accum)
// ---------------------------------------------------------------------------
#define MMA_BF16(d, a, b)                                                     \
    asm volatile(                                                             \
        "mma.sync.aligned.m16n8k16.row.col.f32.bf16.bf16.f32 "                \
        "{%0,%1,%2,%3},{%4,%5,%6,%7},{%8,%9},{%0,%1,%2,%3};"                  \
        : "+f"((d)[0]), "+f"((d)[1]), "+f"((d)[2]), "+f"((d)[3])              \
        : "r"((a)[0]), "r"((a)[1]), "r"((a)[2]), "r"((a)[3]),                 \
          "r"((b)[0]), "r"((b)[1]))

// Shared-memory layout (dynamic; 53248 bytes > 48KB static limit)
struct ConvSM {
    uint32_t xh[64][36];    // X packed hi: stride 36 -> bank 4qr+qc, CF
    uint32_t xl[64][36];
    uint32_t wh[32][136];   // W packed hi: stride 136 -> bank 8qc+qr, CF
    uint32_t wl[32][136];
};
#define CONV_SMEM_BYTES (sizeof(ConvSM))   // 53248

// ---------------------------------------------------------------------------
// bf16 3-pass compensated conv layer:
//   out = [agg | h] @ [[W_rel],[W_root]] + b_rel     (K=256, Ncols=128)
// MODE 0: relu -> LN     MODE 1: +h -> relu -> LN     MODE 2: plain
//
// Block 256 thr (8 warps), tile 64 rows x 128 cols; warp grid 2x4, warp
// tile 32x32. K in 4 stages of 64 (4 k16 MMA substeps per stage).
// All operands packed bf16x2 along k. W pre-split (g_whi/g_wlo).
// ---------------------------------------------------------------------------
template <int MODE>
__global__ __launch_bounds__(256)
void conv_bf_kernel(const float* __restrict__ agg,
                    const float* __restrict__ hin,
                    const uint32_t* __restrict__ whi,  // [128 kp][136]
                    const uint32_t* __restrict__ wlo,
                    const float* __restrict__ br,
                    const float* __restrict__ gamma,
                    const float* __restrict__ beta,
                    float* __restrict__ out,
                    int Nn)
{
    extern __shared__ char smraw[];
    ConvSM& s = *reinterpret_cast<ConvSM*>(smraw);
    float (*ob)[132] = reinterpret_cast<float(*)[132]>(smraw);  // epilogue overlay

    const int tid  = threadIdx.x;
    const int lane = tid & 31;
    const int wid  = tid >> 5;
    const int wr   = wid >> 2;       // warp row: 0..1
    const int wc   = wid & 3;        // warp col: 0..3
    const int rowBase = blockIdx.x * 64;
    const int qr = lane >> 2;        // 0..7
    const int qc = lane & 3;         // 0..3

    float acc[2][4][4];
#pragma unroll
    for (int m = 0; m < 2; m++)
#pragma unroll
        for (int n = 0; n < 4; n++)
#pragma unroll
            for (int j = 0; j < 4; j++) acc[m][n][j] = 0.0f;

#pragma unroll
    for (int kt = 0; kt < 4; kt++) {
        // X source for this 64-wide k slice: stages 0,1 -> agg; 2,3 -> hin
        const float* xbase = (kt < 2) ? (agg + kt * 64)
                                      : (hin + (kt - 2) * 64);

        // ---- load X tile (64 rows x 64 k) as packed bf16x2 hi/lo ----
#pragma unroll
        for (int p = 0; p < 4; p++) {
            int cidx = tid + p * 256;         // 0..1023
            int m  = cidx >> 4;               // row 0..63
            int kq = cidx & 15;               // float4 chunk 0..15
            int r  = rowBase + m;
            float4 v = (r < Nn)
                ? *reinterpret_cast<const float4*>(xbase + (size_t)r * DNN + kq * 4)
                : make_float4(0.f, 0.f, 0.f, 0.f);
            uint32_t h0, l0, h1, l1;
            bfsplit2(v.x, v.y, h0, l0);
            bfsplit2(v.z, v.w, h1, l1);
            s.xh[m][kq * 2]     = h0;
            s.xl[m][kq * 2]     = l0;
            s.xh[m][kq * 2 + 1] = h1;
            s.xl[m][kq * 2 + 1] = l1;
        }

        // ---- load W tile (32 k-pairs x 128 cols), straight uint4 copy ----
#pragma unroll
        for (int p = 0; p < 4; p++) {
            int q  = tid + p * 256;           // 0..1023
            int kp = q >> 5;                  // 0..31
            int c4 = (q & 31) * 4;            // 0..124
            size_t go = (size_t)(kt * 32 + kp) * WPSTRIDE + c4;
            *reinterpret_cast<uint4*>(&s.wh[kp][c4]) =
                *reinterpret_cast<const uint4*>(whi + go);
            *reinterpret_cast<uint4*>(&s.wl[kp][c4]) =
                *reinterpret_cast<const uint4*>(wlo + go);
        }

        __syncthreads();

        // ---- 4 k16 substeps ----
#pragma unroll
        for (int ks = 0; ks < 4; ks++) {
            const int kp0 = ks * 8;

            uint32_t Ah[2][4], Al[2][4], Bh[4][2], Bl[4][2];
#pragma unroll
            for (int m = 0; m < 2; m++) {
                int r = wr * 32 + m * 16 + qr;
                Ah[m][0] = s.xh[r    ][kp0 + qc    ];
                Ah[m][1] = s.xh[r + 8][kp0 + qc    ];
                Ah[m][2] = s.xh[r    ][kp0 + qc + 4];
                Ah[m][3] = s.xh[r + 8][kp0 + qc + 4];
                Al[m][0] = s.xl[r    ][kp0 + qc    ];
                Al[m][1] = s.xl[r + 8][kp0 + qc    ];
                Al[m][2] = s.xl[r    ][kp0 + qc + 4];
                Al[m][3] = s.xl[r + 8][kp0 + qc + 4];
            }
#pragma unroll
            for (int n = 0; n < 4; n++) {
                int col = wc * 32 + n * 8 + qr;
                Bh[n][0] = s.wh[kp0 + qc    ][col];
                Bh[n][1] = s.wh[kp0 + qc + 4][col];
                Bl[n][0] = s.wl[kp0 + qc    ][col];
                Bl[n][1] = s.wl[kp0 + qc + 4][col];
            }

#pragma unroll
            for (int m = 0; m < 2; m++)
#pragma unroll
                for (int n = 0; n < 4; n++) {
                    MMA_BF16(acc[m][n], Ah[m], Bh[n]);
                    MMA_BF16(acc[m][n], Ah[m], Bl[n]);
                    MMA_BF16(acc[m][n], Al[m], Bh[n]);
                }
        }

        __syncthreads();
    }

    // ---- epilogue: acc -> smem (overlay), then per-row LayerNorm ----
#pragma unroll
    for (int m = 0; m < 2; m++) {
        int r0 = wr * 32 + m * 16 + qr;
#pragma unroll
        for (int n = 0; n < 4; n++) {
            int c = wc * 32 + n * 8 + qc * 2;
            ob[r0    ][c    ] = acc[m][n][0];
            ob[r0    ][c + 1] = acc[m][n][1];
            ob[r0 + 8][c    ] = acc[m][n][2];
            ob[r0 + 8][c + 1] = acc[m][n][3];
        }
    }
    __syncthreads();

    // Warp wid handles rows wid*8 .. wid*8+7; lane holds 4 cols (lane*4).
    const int c0 = lane * 4;
    const float4 bv = *reinterpret_cast<const float4*>(br + c0);
    float4 gv, btv;
    if (MODE < 2) {
        gv  = *reinterpret_cast<const float4*>(gamma + c0);
        btv = *reinterpret_cast<const float4*>(beta  + c0);
    }

#pragma unroll
    for (int i = 0; i < 8; i++) {
        int lr = wid * 8 + i;
        int r  = rowBase + lr;
        bool valid = (r < Nn);

        float4 v = *reinterpret_cast<const float4*>(&ob[lr][c0]);
        float v0 = v.x + bv.x;
        float v1 = v.y + bv.y;
        float v2 = v.z + bv.z;
        float v3 = v.w + bv.w;

        if (MODE == 1) {
            if (valid) {
                float4 hr = *reinterpret_cast<const float4*>(hin + (size_t)r * DNN + c0);
                v0 += hr.x; v1 += hr.y; v2 += hr.z; v3 += hr.w;
            }
        }

        if (MODE < 2) {
            v0 = fmaxf(v0, 0.0f);
            v1 = fmaxf(v1, 0.0f);
            v2 = fmaxf(v2, 0.0f);
            v3 = fmaxf(v3, 0.0f);

            float su = v0 + v1 + v2 + v3;
            float s2 = v0 * v0 + v1 * v1 + v2 * v2 + v3 * v3;
#pragma unroll
            for (int off = 16; off >= 1; off >>= 1) {
                su += __shfl_xor_sync(0xFFFFFFFFu, su, off);
                s2 += __shfl_xor_sync(0xFFFFFFFFu, s2, off);
            }
            float mean = su * (1.0f / 128.0f);
            float var  = s2 * (1.0f / 128.0f) - mean * mean;
            float inv  = rsqrtf(var + EPS);

            v0 = (v0 - mean) * inv * gv.x + btv.x;
            v1 = (v1 - mean) * inv * gv.y + btv.y;
            v2 = (v2 - mean) * inv * gv.z + btv.z;
            v3 = (v3 - mean) * inv * gv.w + btv.w;
        }

        if (valid) {
            *reinterpret_cast<float4*>(out + (size_t)r * DNN + c0) =
                make_float4(v0, v1, v2, v3);
        }
    }
}

// ---------------------------------------------------------------------------
// Launch.  Inputs: in_feat[N,128] f32, edge_index[2,E] i32,
// W_rel[4,128,128], b_rel[4,128], W_root[4,128,128], ln_gamma[128],
// ln_beta[128].  Output: [N,128] f32.
// ---------------------------------------------------------------------------
extern "C" void kernel_launch(void* const* d_in, const int* in_sizes, int n_in,
                              void* d_out, int out_size)
{
    const float* in_feat = (const float*)d_in[0];
    const int*   ei      = (const int*)  d_in[1];
    const float* W_rel   = (const float*)d_in[2];
    const float* b_rel   = (const float*)d_in[3];
    const float* W_root  = (const float*)d_in[4];
    const float* gamma   = (const float*)d_in[5];
    const float* beta    = (const float*)d_in[6];
    float* out = (float*)d_out;

    const int Nn = in_sizes[0] / DNN;
    const int E  = in_sizes[1] / 2;
    const int* src = ei;
    const int* dst = ei + E;

    float *agg, *h0, *h1;
    int *deg, *off, *cur, *esrc;
    uint32_t *whi, *wlo;
    cudaGetSymbolAddress((void**)&agg,  g_agg);
    cudaGetSymbolAddress((void**)&h0,   g_h0);
    cudaGetSymbolAddress((void**)&h1,   g_h1);
    cudaGetSymbolAddress((void**)&deg,  g_deg);
    cudaGetSymbolAddress((void**)&off,  g_off);
    cudaGetSymbolAddress((void**)&cur,  g_cursor);
    cudaGetSymbolAddress((void**)&esrc, g_esrc);
    cudaGetSymbolAddress((void**)&whi,  g_whi);
    cudaGetSymbolAddress((void**)&wlo,  g_wlo);

    // Allow >48KB dynamic smem for the conv kernels (idempotent, capture-safe)
    cudaFuncSetAttribute(conv_bf_kernel<0>,
                         cudaFuncAttributeMaxDynamicSharedMemorySize, CONV_SMEM_BYTES);
    cudaFuncSetAttribute(conv_bf_kernel<1>,
                         cudaFuncAttributeMaxDynamicSharedMemorySize, CONV_SMEM_BYTES);
    cudaFuncSetAttribute(conv_bf_kernel<2>,
                         cudaFuncAttributeMaxDynamicSharedMemorySize, CONV_SMEM_BYTES);

    const int edgeBlocks   = (E + 255) / 256;
    const int gatherBlocks = (Nn + 7) / 8;
    const int convBlocks   = (Nn + 63) / 64;
    const size_t WPL       = (size_t)128 * WPSTRIDE;   // per-layer packed stride

    // ---- W split (once) + CSR build (once) ----
    wsplit_kernel<<<(4 * 128 * 128 + 255) / 256, 256>>>(W_rel, W_root, whi, wlo);
    cudaMemsetAsync(deg, 0, (size_t)(Nn + 1) * sizeof(int));
    hist_kernel<<<edgeBlocks, 256>>>(dst, deg, E);
    scan_kernel<<<1, 1024>>>(deg, off, cur, Nn, E);
    reorder_kernel<<<edgeBlocks, 256>>>(src, dst, cur, esrc, E);

    // ---- Layer 0: conv(in_feat) -> relu -> LN  => h0 ----
    gather_kernel<<<gatherBlocks, 256>>>(in_feat, esrc, off, agg, Nn);
    conv_bf_kernel<0><<<convBlocks, 256, CONV_SMEM_BYTES>>>(
        agg, in_feat, whi + 0 * WPL, wlo + 0 * WPL,
        b_rel + 0 * DNN, gamma, beta, h0, Nn);

    // ---- Layer 1: conv(h0) + h0 -> relu -> LN  => h1 ----
    gather_kernel<<<gatherBlocks, 256>>>(h0, esrc, off, agg, Nn);
    conv_bf_kernel<1><<<convBlocks, 256, CONV_SMEM_BYTES>>>(
        agg, h0, whi + 1 * WPL, wlo + 1 * WPL,
        b_rel + 1 * DNN, gamma, beta, h1, Nn);

    // ---- Layer 2: conv(h1) + h1 -> relu -> LN  => h0 ----
    gather_kernel<<<gatherBlocks, 256>>>(h1, esrc, off, agg, Nn);
    conv_bf_kernel<1><<<convBlocks, 256, CONV_SMEM_BYTES>>>(
        agg, h1, whi + 2 * WPL, wlo + 2 * WPL,
        b_rel + 2 * DNN, gamma, beta, h0, Nn);

    // ---- Layer 3 (output): conv(h0) only => d_out ----
    gather_kernel<<<gatherBlocks, 256>>>(h0, esrc, off, agg, Nn);
    conv_bf_kernel<2><<<convBlocks, 256, CONV_SMEM_BYTES>>>(
        agg, h0, whi + 3 * WPL, wlo + 3 * WPL,
        b_rel + 3 * DNN, gamma, beta, out, Nn);
}